// round 6
// baseline (speedup 1.0000x reference)
#include <cuda_runtime.h>
#include <cstdint>
#include <math.h>

#define NPTS    4096
#define MAXQ    32768             // B=8 * 4096
#define THREADS 256
#define QPT     4                 // queries per thread (2 packed pairs)
#define QPB     (THREADS * QPT)   // 1024 queries per block
#define JCHUNK  128               // candidates per block
#define NCHUNK  (NPTS / JCHUNK)   // 32
#define NGROUP  32                // argmin recovery granularity
#define NGROUPS (JCHUNK / NGROUP) // 4
#define MLANES  4                 // merge lanes per query

typedef unsigned long long ull;

// Per (dir, chunk, query): (fkey(e_min) << 32) | group_start_index_within_batch
__device__ ull g_part[2][NCHUNK][MAXQ];

__device__ __forceinline__ ull fma2(ull a, ull b, ull c) {
    ull d;
    asm("fma.rn.f32x2 %0, %1, %2, %3;" : "=l"(d) : "l"(a), "l"(b), "l"(c));
    return d;
}
__device__ __forceinline__ ull pack2(float lo, float hi) {
    ull d;
    asm("mov.b64 %0, {%1, %2};" : "=l"(d) : "f"(lo), "f"(hi));
    return d;
}
__device__ __forceinline__ ull dup2(float v) {
    ull d;
    asm("mov.b64 %0, {%1, %1};" : "=l"(d) : "f"(v));
    return d;
}
__device__ __forceinline__ float lof(ull v) { return __uint_as_float((unsigned int)v); }
__device__ __forceinline__ float hif(ull v) { return __uint_as_float((unsigned int)(v >> 32)); }

// Order-preserving float -> uint32 (total order incl. negatives).
__device__ __forceinline__ unsigned int fkey(float f) {
    unsigned int b = __float_as_uint(f);
    return (b & 0x80000000u) ? ~b : (b | 0x80000000u);
}

// NN kernel: per query, min over candidates of e = |c|^2 - 2<q,c>
// (argmin(e) == argmin(d)). Queries packed 2-per-f32x2 (held in registers);
// candidates duplicated in an smem tile (broadcast LDS.128). Exact index
// recovered later by rescanning the winning 32-candidate group.
__global__ void __launch_bounds__(THREADS, 5) nn_kernel(
    const float* __restrict__ X1, const float* __restrict__ X2, float* out)
{
    __shared__ __align__(16) ull tile[JCHUNK][4];   // {xx, yy, zz, ww} dup'd

    const int dir   = blockIdx.z;              // 0: Q=X1,C=X2   1: Q=X2,C=X1
    const float* __restrict__ Q = dir ? X2 : X1;
    const float* __restrict__ C = dir ? X1 : X2;

    const int tid   = threadIdx.x;
    const int chunk = blockIdx.x;              // 0..NCHUNK-1
    const int qbase = blockIdx.y * QPB;
    const int batch = qbase / NPTS;            // QPB divides NPTS
    const int jloc  = chunk * JCHUNK;          // candidate base within batch

    if (chunk == 0 && blockIdx.y == 0 && dir == 0 && tid == 0)
        out[0] = 0.0f;                         // merge accumulates into out

    if (tid < JCHUNK) {
        const float* p = C + (size_t)(batch * NPTS + jloc + tid) * 6;
        float x = p[0], y = p[1], z = p[2];
        tile[tid][0] = dup2(x);
        tile[tid][1] = dup2(y);
        tile[tid][2] = dup2(z);
        tile[tid][3] = dup2(fmaf(x, x, fmaf(y, y, z * z)));
    }
    __syncthreads();

    // 4 consecutive queries per thread; -2 folded in (exact).
    const int q0 = qbase + tid * QPT;
    ull qx01, qy01, qz01, qx23, qy23, qz23;
    {
        const float* a = Q + (size_t)q0 * 6;
        qx01 = pack2(-2.0f * a[0],  -2.0f * a[6]);
        qy01 = pack2(-2.0f * a[1],  -2.0f * a[7]);
        qz01 = pack2(-2.0f * a[2],  -2.0f * a[8]);
        qx23 = pack2(-2.0f * a[12], -2.0f * a[18]);
        qy23 = pack2(-2.0f * a[13], -2.0f * a[19]);
        qz23 = pack2(-2.0f * a[14], -2.0f * a[20]);
    }

    float beste[QPT];
    int   bestg[QPT];
#pragma unroll
    for (int k = 0; k < QPT; k++) { beste[k] = 3.4e38f; bestg[k] = 0; }

    const ulonglong2* tp = (const ulonglong2*)&tile[0][0];
#pragma unroll 1
    for (int g = 0; g < NGROUPS; g++) {
        float g0 = 3.4e38f, g1 = 3.4e38f, g2 = 3.4e38f, g3 = 3.4e38f;
#pragma unroll 4
        for (int cc = 0; cc < NGROUP; cc++) {
            ulonglong2 A = tp[0];              // xx, yy
            ulonglong2 B = tp[1];              // zz, ww
            tp += 2;
            ull t0 = fma2(qz01, B.x, B.y);
            t0 = fma2(qy01, A.y, t0);
            t0 = fma2(qx01, A.x, t0);          // e for q0, q1
            ull t1 = fma2(qz23, B.x, B.y);
            t1 = fma2(qy23, A.y, t1);
            t1 = fma2(qx23, A.x, t1);          // e for q2, q3
            g0 = fminf(g0, lof(t0));
            g1 = fminf(g1, hif(t0));
            g2 = fminf(g2, lof(t1));
            g3 = fminf(g3, hif(t1));
        }
        if (g0 < beste[0]) { beste[0] = g0; bestg[0] = g; }
        if (g1 < beste[1]) { beste[1] = g1; bestg[1] = g; }
        if (g2 < beste[2]) { beste[2] = g2; bestg[2] = g; }
        if (g3 < beste[3]) { beste[3] = g3; bestg[3] = g; }
    }

#pragma unroll
    for (int k = 0; k < QPT; k++) {
        unsigned int start = (unsigned int)(jloc + bestg[k] * NGROUP);
        g_part[dir][chunk][q0 + k] = ((ull)fkey(beste[k]) << 32) | start;
    }
}

__device__ __forceinline__ float normal_diff2(const float* __restrict__ a,
                                              const float* __restrict__ b) {
    float ax = a[0], ay = a[1], az = a[2];
    float bx = b[0], by = b[1], bz = b[2];
    float ia = 1.0f / fmaxf(sqrtf(fmaf(ax, ax, fmaf(ay, ay, az * az))), 1e-12f);
    float ib = 1.0f / fmaxf(sqrtf(fmaf(bx, bx, fmaf(by, by, bz * bz))), 1e-12f);
    float dx = ax * ia - bx * ib;
    float dy = ay * ia - by * ib;
    float dz = az * ia - bz * ib;
    return fmaf(dx, dx, fmaf(dy, dy, dz * dz));
}

// Merge: 4 lanes per query. Lanes min the 32 chunk partials (u64 min keeps
// first-occurrence ties), rescan the winning 32-candidate group with the
// bit-identical scalar chain (8 candidates per lane, high MLP), then lane 0
// adds the per-query contribution; block partial -> one atomicAdd.
__global__ void __launch_bounds__(THREADS) merge_kernel(
    const float* __restrict__ X1, const float* __restrict__ X2,
    float* __restrict__ out, int nq, float inv_nq)
{
    const int tid  = threadIdx.x;
    const int l    = tid & (MLANES - 1);
    const int gi   = (blockIdx.x * THREADS + tid) / MLANES;   // query slot
    const int dir  = gi >= nq;
    const int q    = dir ? gi - nq : gi;
    const int batch = q / NPTS;

    // 1) min over NCHUNK=32 partials, 8 per lane, 4-lane xor reduce
    ull best = ~0ull;
#pragma unroll
    for (int s = 0; s < NCHUNK / MLANES; s++) {
        ull v = g_part[dir][l + s * MLANES][q];
        best = v < best ? v : best;
    }
#pragma unroll
    for (int m = MLANES / 2; m >= 1; m >>= 1) {
        ull o = __shfl_xor_sync(0xFFFFFFFFu, best, m);
        best = o < best ? o : best;
    }
    int start = (int)(best & 0xFFFFFFFFull);               // within batch

    // 2) rescan 32 candidates, 8 per lane (bit-identical chain)
    const float* __restrict__ Qb = dir ? X2 : X1;
    const float* __restrict__ Cb = dir ? X1 : X2;
    const float* qp = Qb + (size_t)q * 6;
    float qx = qp[0], qy = qp[1], qz = qp[2];
    float nxs = -2.0f * qx, nys = -2.0f * qy, nzs = -2.0f * qz;

    const float2* cb2 = (const float2*)(Cb + (size_t)(batch * NPTS + start + l * 8) * 6);
    float2 f0[8], f1[8];
#pragma unroll
    for (int j = 0; j < 8; j++) {          // 16 independent LDG.64
        f0[j] = cb2[j * 3 + 0];            // x, y
        f1[j] = cb2[j * 3 + 1];            // z, nx
    }
    float be = 3.4e38f;
    int   bi = 0;
#pragma unroll
    for (int j = 0; j < 8; j++) {
        float cx = f0[j].x, cy = f0[j].y, cz = f1[j].x;
        float cw = fmaf(cx, cx, fmaf(cy, cy, cz * cz));
        float t  = fmaf(nxs, cx, fmaf(nys, cy, fmaf(nzs, cz, cw)));
        if (t < be) { be = t; bi = j; }                    // strict <: first min
    }
    ull bk = ((ull)fkey(be) << 32) | (unsigned int)(l * 8 + bi);
#pragma unroll
    for (int m = MLANES / 2; m >= 1; m >>= 1) {
        ull o = __shfl_xor_sync(0xFFFFFFFFu, bk, m);
        bk = o < bk ? o : bk;                              // tie -> smaller idx
    }

    // 3) lane 0 computes the per-query contribution
    float acc = 0.0f;
    if (l == 0) {
        int idx = start + (int)(bk & 31u);
        unsigned int ek = (unsigned int)(bk >> 32);
        float e = __uint_as_float((ek & 0x80000000u) ? (ek & 0x7FFFFFFFu) : ~ek);
        float sq = fmaf(qx, qx, fmaf(qy, qy, qz * qz));
        const float* cn = Cb + (size_t)(batch * NPTS + idx) * 6 + 3;
        acc = (sq + e) + normal_diff2(qp + 3, cn);
    }

    // block reduction -> single atomic per block
    __shared__ float ssum[THREADS / 32];
    float v = acc;
#pragma unroll
    for (int o = 16; o > 0; o >>= 1) v += __shfl_down_sync(0xFFFFFFFFu, v, o);
    int lane = tid & 31, warp = tid >> 5;
    if (lane == 0) ssum[warp] = v;
    __syncthreads();
    if (warp == 0) {
        v = (lane < THREADS / 32) ? ssum[lane] : 0.0f;
#pragma unroll
        for (int o = 4; o > 0; o >>= 1) v += __shfl_down_sync(0xFFFFFFFFu, v, o);
        if (lane == 0) atomicAdd(out, v * inv_nq);
    }
}

extern "C" void kernel_launch(void* const* d_in, const int* in_sizes, int n_in,
                              void* d_out, int out_size)
{
    const float* x1 = (const float*)d_in[0];
    const float* x2 = (const float*)d_in[1];
    float* out = (float*)d_out;

    int total = in_sizes[0];
    int B  = total / (NPTS * 6);      // 8
    int nq = B * NPTS;                // 32768

    dim3 grid(NCHUNK, nq / QPB, 2);   // (32, 32, 2) = 2048 CTAs
    nn_kernel<<<grid, THREADS>>>(x1, x2, out);

    // 2*nq queries * MLANES / THREADS = 1024 blocks
    int mblocks = 2 * nq * MLANES / THREADS;
    merge_kernel<<<mblocks, THREADS>>>(x1, x2, out, nq, 1.0f / (float)nq);
}

// round 7
// speedup vs baseline: 1.0703x; 1.0703x over previous
#include <cuda_runtime.h>
#include <cstdint>
#include <math.h>

#define NPTS    4096
#define MAXQ    32768             // B=8 * 4096
#define THREADS 256
#define QPT     4                 // queries per thread (2 packed f32x2 pairs)
#define QPB     (THREADS * QPT)   // 1024 queries per block
#define JCHUNK  128               // candidates per block
#define NCHUNK  (NPTS / JCHUNK)   // 32
#define NGROUP  32                // argmin recovery granularity
#define NGROUPS (JCHUNK / NGROUP) // 4
#define MLANES  8                 // merge lanes per query

typedef unsigned long long ull;

// Global best per (dir, query): (fkey(e_min) << 32) | group_start_within_batch
__device__ ull g_best[2][MAXQ];

__device__ __forceinline__ ull fma2(ull a, ull b, ull c) {
    ull d;
    asm("fma.rn.f32x2 %0, %1, %2, %3;" : "=l"(d) : "l"(a), "l"(b), "l"(c));
    return d;
}
__device__ __forceinline__ ull pack2(float lo, float hi) {
    ull d;
    asm("mov.b64 %0, {%1, %2};" : "=l"(d) : "f"(lo), "f"(hi));
    return d;
}
__device__ __forceinline__ ull dup2(float v) {
    ull d;
    asm("mov.b64 %0, {%1, %1};" : "=l"(d) : "f"(v));
    return d;
}
__device__ __forceinline__ float lof(ull v) { return __uint_as_float((unsigned int)v); }
__device__ __forceinline__ float hif(ull v) { return __uint_as_float((unsigned int)(v >> 32)); }

// Order-preserving float -> uint32 (total order incl. negatives).
__device__ __forceinline__ unsigned int fkey(float f) {
    unsigned int b = __float_as_uint(f);
    return (b & 0x80000000u) ? ~b : (b | 0x80000000u);
}

__global__ void __launch_bounds__(THREADS) init_kernel(float* out) {
    int i = blockIdx.x * THREADS + threadIdx.x;
    g_best[0][i] = ~0ull;
    g_best[1][i] = ~0ull;
    if (i == 0) out[0] = 0.0f;
}

// NN kernel: per query, min over candidates of e = |c|^2 - 2<q,c>
// (argmin(e) == argmin(d)). Queries packed 2-per-f32x2 in registers;
// candidates duplicated in smem (broadcast LDS.128) with a rolling
// one-candidate register prefetch to decouple load-to-use stalls.
// Cross-chunk reduction folded in via fire-and-forget atomicMin(u64).
__global__ void __launch_bounds__(THREADS, 5) nn_kernel(
    const float* __restrict__ X1, const float* __restrict__ X2)
{
    __shared__ __align__(16) ull tile[(JCHUNK + 1) * 4];   // {xx,yy,zz,ww} + pad

    const int dir   = blockIdx.z;              // 0: Q=X1,C=X2   1: Q=X2,C=X1
    const float* __restrict__ Q = dir ? X2 : X1;
    const float* __restrict__ C = dir ? X1 : X2;

    const int tid   = threadIdx.x;
    const int chunk = blockIdx.x;              // 0..NCHUNK-1
    const int qbase = blockIdx.y * QPB;
    const int batch = qbase / NPTS;            // QPB divides NPTS
    const int jloc  = chunk * JCHUNK;          // candidate base within batch

    if (tid < JCHUNK) {
        const float* p = C + (size_t)(batch * NPTS + jloc + tid) * 6;
        float x = p[0], y = p[1], z = p[2];
        tile[tid * 4 + 0] = dup2(x);
        tile[tid * 4 + 1] = dup2(y);
        tile[tid * 4 + 2] = dup2(z);
        tile[tid * 4 + 3] = dup2(fmaf(x, x, fmaf(y, y, z * z)));
    } else if (tid < JCHUNK + 32) {            // pad row (prefetch overrun)
        if (tid == JCHUNK) {
            tile[JCHUNK * 4 + 0] = 0; tile[JCHUNK * 4 + 1] = 0;
            tile[JCHUNK * 4 + 2] = 0; tile[JCHUNK * 4 + 3] = 0;
        }
    }
    __syncthreads();

    // 4 consecutive queries per thread; -2 folded in (exact).
    const int q0 = qbase + tid * QPT;
    ull qx01, qy01, qz01, qx23, qy23, qz23;
    {
        const float* a = Q + (size_t)q0 * 6;
        qx01 = pack2(-2.0f * a[0],  -2.0f * a[6]);
        qy01 = pack2(-2.0f * a[1],  -2.0f * a[7]);
        qz01 = pack2(-2.0f * a[2],  -2.0f * a[8]);
        qx23 = pack2(-2.0f * a[12], -2.0f * a[18]);
        qy23 = pack2(-2.0f * a[13], -2.0f * a[19]);
        qz23 = pack2(-2.0f * a[14], -2.0f * a[20]);
    }

    float beste[QPT];
    int   bestg[QPT];
#pragma unroll
    for (int k = 0; k < QPT; k++) { beste[k] = 3.4e38f; bestg[k] = 0; }

    const ulonglong2* tp = (const ulonglong2*)tile;
    ulonglong2 A = tp[0];                      // rolling prefetch registers
    ulonglong2 Bv = tp[1];
    tp += 2;

#pragma unroll 1
    for (int g = 0; g < NGROUPS; g++) {
        float g0 = 3.4e38f, g1 = 3.4e38f, g2 = 3.4e38f, g3 = 3.4e38f;
#pragma unroll 8
        for (int cc = 0; cc < NGROUP; cc++) {
            ulonglong2 An = tp[0];             // prefetch next candidate
            ulonglong2 Bn = tp[1];
            tp += 2;
            ull t0 = fma2(qz01, Bv.x, Bv.y);
            ull t1 = fma2(qz23, Bv.x, Bv.y);
            t0 = fma2(qy01, A.y, t0);
            t1 = fma2(qy23, A.y, t1);
            t0 = fma2(qx01, A.x, t0);          // e for q0,q1
            t1 = fma2(qx23, A.x, t1);          // e for q2,q3
            g0 = fminf(g0, lof(t0));
            g1 = fminf(g1, hif(t0));
            g2 = fminf(g2, lof(t1));
            g3 = fminf(g3, hif(t1));
            A = An; Bv = Bn;
        }
        if (g0 < beste[0]) { beste[0] = g0; bestg[0] = g; }
        if (g1 < beste[1]) { beste[1] = g1; bestg[1] = g; }
        if (g2 < beste[2]) { beste[2] = g2; bestg[2] = g; }
        if (g3 < beste[3]) { beste[3] = g3; bestg[3] = g; }
    }

#pragma unroll
    for (int k = 0; k < QPT; k++) {
        unsigned int start = (unsigned int)(jloc + bestg[k] * NGROUP);
        atomicMin(&g_best[dir][q0 + k], ((ull)fkey(beste[k]) << 32) | start);
    }
}

__device__ __forceinline__ float normal_diff2(const float* __restrict__ a,
                                              const float* __restrict__ b) {
    float ax = a[0], ay = a[1], az = a[2];
    float bx = b[0], by = b[1], bz = b[2];
    float ia = 1.0f / fmaxf(sqrtf(fmaf(ax, ax, fmaf(ay, ay, az * az))), 1e-12f);
    float ib = 1.0f / fmaxf(sqrtf(fmaf(bx, bx, fmaf(by, by, bz * bz))), 1e-12f);
    float dx = ax * ia - bx * ib;
    float dy = ay * ia - by * ib;
    float dz = az * ia - bz * ib;
    return fmaf(dx, dx, fmaf(dy, dy, dz * dz));
}

// Merge: 8 lanes per query. Read the winning (e, group-start) record, rescan
// the 32-candidate group with the bit-identical scalar chain (4 per lane,
// high MLP), cross-lane argmin via packed (fkey << 32 | local_idx), lane 0
// computes the contribution; block partial -> one atomicAdd.
__global__ void __launch_bounds__(THREADS) merge_kernel(
    const float* __restrict__ X1, const float* __restrict__ X2,
    float* __restrict__ out, int nq, float inv_nq)
{
    const int tid  = threadIdx.x;
    const int l    = tid & (MLANES - 1);
    const int gi   = (blockIdx.x * THREADS + tid) / MLANES;   // query slot
    const int dir  = gi >= nq;
    const int q    = dir ? gi - nq : gi;
    const int batch = q / NPTS;

    ull best = g_best[dir][q];                 // broadcast load
    int start = (int)(best & 0xFFFFFFFFull);   // within batch

    const float* __restrict__ Qb = dir ? X2 : X1;
    const float* __restrict__ Cb = dir ? X1 : X2;
    const float* qp = Qb + (size_t)q * 6;
    float qx = qp[0], qy = qp[1], qz = qp[2];
    float nxs = -2.0f * qx, nys = -2.0f * qy, nzs = -2.0f * qz;

    const float2* cb2 = (const float2*)(Cb + (size_t)(batch * NPTS + start + l * 4) * 6);
    float2 f0[4], f1[4];
#pragma unroll
    for (int j = 0; j < 4; j++) {              // 8 independent LDG.64
        f0[j] = cb2[j * 3 + 0];                // x, y
        f1[j] = cb2[j * 3 + 1];                // z, nx
    }
    float be = 3.4e38f;
    int   bi = 0;
#pragma unroll
    for (int j = 0; j < 4; j++) {
        float cx = f0[j].x, cy = f0[j].y, cz = f1[j].x;
        float cw = fmaf(cx, cx, fmaf(cy, cy, cz * cz));
        float t  = fmaf(nxs, cx, fmaf(nys, cy, fmaf(nzs, cz, cw)));
        if (t < be) { be = t; bi = j; }        // strict <: first min
    }
    ull bk = ((ull)fkey(be) << 32) | (unsigned int)(l * 4 + bi);
#pragma unroll
    for (int m = MLANES / 2; m >= 1; m >>= 1) {
        ull o = __shfl_xor_sync(0xFFFFFFFFu, bk, m);
        bk = o < bk ? o : bk;                  // tie -> smaller idx
    }

    float acc = 0.0f;
    if (l == 0) {
        int idx = start + (int)(bk & 31u);
        unsigned int ek = (unsigned int)(bk >> 32);
        float e = __uint_as_float((ek & 0x80000000u) ? (ek & 0x7FFFFFFFu) : ~ek);
        float sq = fmaf(qx, qx, fmaf(qy, qy, qz * qz));
        const float* cn = Cb + (size_t)(batch * NPTS + idx) * 6 + 3;
        acc = (sq + e) + normal_diff2(qp + 3, cn);
    }

    __shared__ float ssum[THREADS / 32];
    float v = acc;
#pragma unroll
    for (int o = 16; o > 0; o >>= 1) v += __shfl_down_sync(0xFFFFFFFFu, v, o);
    int lane = tid & 31, warp = tid >> 5;
    if (lane == 0) ssum[warp] = v;
    __syncthreads();
    if (warp == 0) {
        v = (lane < THREADS / 32) ? ssum[lane] : 0.0f;
#pragma unroll
        for (int o = 4; o > 0; o >>= 1) v += __shfl_down_sync(0xFFFFFFFFu, v, o);
        if (lane == 0) atomicAdd(out, v * inv_nq);
    }
}

extern "C" void kernel_launch(void* const* d_in, const int* in_sizes, int n_in,
                              void* d_out, int out_size)
{
    const float* x1 = (const float*)d_in[0];
    const float* x2 = (const float*)d_in[1];
    float* out = (float*)d_out;

    int total = in_sizes[0];
    int B  = total / (NPTS * 6);      // 8
    int nq = B * NPTS;                // 32768

    init_kernel<<<MAXQ / THREADS, THREADS>>>(out);

    dim3 grid(NCHUNK, nq / QPB, 2);   // (32, 32, 2) = 2048 CTAs
    nn_kernel<<<grid, THREADS>>>(x1, x2);

    int mblocks = 2 * nq * MLANES / THREADS;   // 2048
    merge_kernel<<<mblocks, THREADS>>>(x1, x2, out, nq, 1.0f / (float)nq);
}